// round 6
// baseline (speedup 1.0000x reference)
#include <cuda_runtime.h>
#include <cstdint>

typedef unsigned long long ull;

// ---------------- problem constants ----------------
#define B_   4
#define F_   9
#define MP_  100
#define P_   12000
#define C_   64
#define NY_  400
#define NX_  400
#define NXO_ 4          // NX / POOL_W
#define NPTS (B_ * P_)  // 48000
#define NOUT (B_ * C_ * NY_ * NXO_) // 409600

// main kernel tiling
#define TPB  512         // 16 warps
#define NPB  32          // points per block (one per lane)
#define MPT  10          // mp per chunk
#define NCH  (MP_ / MPT) // 10 chunks
#define NBUF 3           // pipeline depth
#define XSN  (F_ * MPT * NPB)   // 2880 floats staged per chunk
#define XSNB (XSN * 4)          // bytes per chunk buffer
#define CPOPS (XSN * 4 / 16)    // 720 cp.async 16B ops per chunk
#define CHF   (MPT * P_)        // float stride between chunks in gmem

// ---------------- staging globals (written by k_setup) ----------------
__device__ ull   g_w1p[F_ * 32];   // packed pairs: [f][q] -> (w1'[2q][f], w1'[2q+1][f])
__device__ ull   g_b1p[32];
__device__ ull   g_w2p[32 * 64];   // [q][c] -> (w2'[2q][c], w2'[2q+1][c])
__device__ ull   g_b2p[32];
__device__ float g_z[C_];

// ---------------- constant copies (filled by D2D memcpy; warp-uniform
// reads from here can be promoted to uniform registers) ------------------
__constant__ ull   c_w1p[F_ * 32];
__constant__ ull   c_b1p[32];
__constant__ ull   c_b2p[32];
__constant__ float c_z[C_];

// ---------------- f32x2 helpers (Blackwell packed fp32) ----------------
__device__ __forceinline__ ull ffma2(ull a, ull b, ull c) {
    ull d;
    asm("fma.rn.f32x2 %0, %1, %2, %3;" : "=l"(d) : "l"(a), "l"(b), "l"(c));
    return d;
}
__device__ __forceinline__ ull fpack(float x, float y) {
    ull r;
    asm("mov.b64 %0, {%1, %2};" : "=l"(r) : "f"(x), "f"(y));
    return r;
}
__device__ __forceinline__ ull fdup(float x) {
    ull r;
    asm("mov.b64 %0, {%1, %2};" : "=l"(r) : "f"(x), "f"(x));
    return r;
}
__device__ __forceinline__ void funpack(ull v, float& x, float& y) {
    asm("mov.b64 {%0, %1}, %2;" : "=f"(x), "=f"(y) : "l"(v));
}
__device__ __forceinline__ ull fmax2(ull a, ull b) {
    float ax, ay, bx, by;
    funpack(a, ax, ay);
    funpack(b, bx, by);
    return fpack(fmaxf(ax, bx), fmaxf(ay, by));
}
__device__ __forceinline__ uint32_t smem_u32(const void* p) {
    return (uint32_t)__cvta_generic_to_shared(p);
}
__device__ __forceinline__ void cp16(uint32_t dst, const float* src) {
    asm volatile("cp.async.ca.shared.global [%0], [%1], 16;" :: "r"(dst), "l"(src));
}

// ---------------- setup: BN fold + weight packing ----------
__global__ void k_setup(const float* __restrict__ w1, const float* __restrict__ b1,
                        const float* __restrict__ g1, const float* __restrict__ be1,
                        const float* __restrict__ m1, const float* __restrict__ v1,
                        const float* __restrict__ w2, const float* __restrict__ b2,
                        const float* __restrict__ g2, const float* __restrict__ be2,
                        const float* __restrict__ m2, const float* __restrict__ v2) {
    __shared__ float s1[C_], bb1[C_], s2[C_], bb2[C_];
    int t = threadIdx.x;
    if (t < C_) {
        float s = g1[t] * rsqrtf(v1[t] + 1e-3f);
        s1[t] = s;
        bb1[t] = b1[t] * s + be1[t] - m1[t] * s;
        float ss = g2[t] * rsqrtf(v2[t] + 1e-3f);
        s2[t] = ss;
        float bz = b2[t] * ss + be2[t] - m2[t] * ss;
        bb2[t] = bz;
        g_z[t] = fmaxf(bz, 0.0f);
    }
    __syncthreads();
    for (int i = t; i < F_ * 32; i += 1024) {
        int f = i / 32, q = i % 32;
        g_w1p[i] = fpack(w1[(2 * q) * F_ + f] * s1[2 * q],
                         w1[(2 * q + 1) * F_ + f] * s1[2 * q + 1]);
    }
    for (int i = t; i < 32 * 64; i += 1024) {
        int q = i / 64, c = i % 64;
        g_w2p[i] = fpack(w2[(2 * q) * C_ + c] * s2[2 * q],
                         w2[(2 * q + 1) * C_ + c] * s2[2 * q + 1]);
    }
    if (t < 32) {
        g_b1p[t] = fpack(bb1[2 * t], bb1[2 * t + 1]);
        g_b2p[t] = fpack(bb2[2 * t], bb2[2 * t + 1]);
    }
}

// init out = relu(b2') everywhere. Every 100-cell pool window contains an
// empty canvas cell (12000 pillars on 160000 cells; P(full window) ~ 1e-112),
// so the empty-cell constant is always a valid atomicMax floor.
__global__ void k_init(float* __restrict__ out) {
    int i = blockIdx.x * blockDim.x + threadIdx.x;   // over NOUT/4 float4 rows
    if (i < NOUT / 4) {
        float zc = c_z[(i / NY_) & (C_ - 1)];
        ((float4*)out)[i] = make_float4(zc, zc, zc, zc);
    }
}

// ---------------- main fused kernel ----------------
// 16 warps (512 thr); lane = point (32 points/block), warp owns 2
// channel-pairs (4 channels) -> only 18 weight pairs per thread, loaded
// once from __constant__ at a warp-uniform index (UR-promotable).
// x staged global->shared via 3-deep cp.async pipeline, one barrier/chunk.
__global__ void __launch_bounds__(TPB, 2) k_main(const float* __restrict__ x,
                                                 const int* __restrict__ coords,
                                                 float* __restrict__ out) {
    __shared__ float xs[NBUF][XSN];
    __shared__ float feat[NPB][65];

    const int tid  = threadIdx.x;
    const int warp = tid >> 5;
    const int lane = tid & 31;
    const int g0   = blockIdx.x * NPB;      // first point id of block
    const int b    = g0 / P_;               // block never crosses batch
    const int pb   = g0 - b * P_;

    // stage-1 weights: 2 channel-pairs, warp-uniform constant reads
    ull w0[F_], w1r[F_];
    #pragma unroll
    for (int f = 0; f < F_; f++) {
        w0[f]  = c_w1p[f * 32 + warp * 2 + 0];
        w1r[f] = c_w1p[f * 32 + warp * 2 + 1];
    }

    const float* xb = x + (size_t)b * (F_ * MP_ * P_) + pb;

    // cp.async assignment: 720 16B ops/chunk, <=2 per thread
    // idx -> f = idx/80, mpi = (idx%80)>>3, quad = idx&7
    const uint32_t xs_base = smem_u32(&xs[0][0]);
    int      cp_soff[2];
    uint32_t cp_doff[2];
    bool     cp_on[2];
    #pragma unroll
    for (int k = 0; k < 2; k++) {
        int idx = tid + k * TPB;
        cp_on[k] = idx < CPOPS;
        int ii   = cp_on[k] ? idx : 0;
        int f    = ii / (MPT * 8);
        int r    = ii - f * (MPT * 8);
        int mpi  = r >> 3;
        int q    = r & 7;
        cp_soff[k] = f * (MP_ * P_) + mpi * P_ + q * 4;
        cp_doff[k] = (uint32_t)(((f * MPT + mpi) * NPB + q * 4) * 4);
    }

    // prologue: prefetch chunks 0 and 1 into bufs 0,1
    #pragma unroll
    for (int k = 0; k < 2; k++)
        if (cp_on[k]) cp16(xs_base + cp_doff[k], xb + cp_soff[k]);
    asm volatile("cp.async.commit_group;");
    #pragma unroll
    for (int k = 0; k < 2; k++)
        if (cp_on[k]) cp16(xs_base + XSNB + cp_doff[k], xb + cp_soff[k] + CHF);
    asm volatile("cp.async.commit_group;");

    ull m0 = 0xFF800000FF800000ull;   // (-inf,-inf)
    ull m1 = 0xFF800000FF800000ull;

    int bufc = 0, bufn = 2;
    #pragma unroll 1
    for (int ch = 0; ch < NCH; ++ch) {
        if (ch < NCH - 1) asm volatile("cp.async.wait_group 1;");
        else              asm volatile("cp.async.wait_group 0;");
        __syncthreads();   // chunk ch visible; all done reading buf[bufn]

        if (ch + 2 < NCH) {   // prefetch chunk ch+2 into bufn
            uint32_t d = xs_base + (uint32_t)bufn * XSNB;
            const float* s = xb + (ch + 2) * CHF;
            #pragma unroll
            for (int k = 0; k < 2; k++)
                if (cp_on[k]) cp16(d + cp_doff[k], s + cp_soff[k]);
            asm volatile("cp.async.commit_group;");
        }

        const float* xc = &xs[bufc][0];
        #pragma unroll
        for (int mpi = 0; mpi < MPT; ++mpi) {
            ull xd0 = fdup(xc[(0 * MPT + mpi) * NPB + lane]);
            ull a0 = ffma2(xd0, w0[0], 0ull);
            ull a1 = ffma2(xd0, w1r[0], 0ull);
            #pragma unroll
            for (int f = 1; f < F_; f++) {
                ull xd = fdup(xc[(f * MPT + mpi) * NPB + lane]);
                a0 = ffma2(xd, w0[f], a0);
                a1 = ffma2(xd, w1r[f], a1);
            }
            m0 = fmax2(m0, a0);
            m1 = fmax2(m1, a1);
        }
        bufc = (bufc == NBUF - 1) ? 0 : bufc + 1;
        bufn = (bufn == NBUF - 1) ? 0 : bufn + 1;
    }

    // bias + ReLU after the max (exact: max_mp(Wx+b) = max_mp(Wx)+b),
    // exchange feat (point-major, padded 65 -> bank-conflict-free)
    {
        float lo, hi, bl, bh;
        funpack(m0, lo, hi);
        funpack(c_b1p[warp * 2 + 0], bl, bh);
        feat[lane][warp * 4 + 0] = fmaxf(lo + bl, 0.0f);
        feat[lane][warp * 4 + 1] = fmaxf(hi + bh, 0.0f);
        funpack(m1, lo, hi);
        funpack(c_b1p[warp * 2 + 1], bl, bh);
        feat[lane][warp * 4 + 2] = fmaxf(lo + bl, 0.0f);
        feat[lane][warp * 4 + 3] = fmaxf(hi + bh, 0.0f);
    }
    __syncthreads();

    // stage 2: 64->64 affine; warp owns 2 output pairs; w2 pairs from
    // global (16KB, L1/L2-resident across all blocks)
    const ull* __restrict__ w2g = g_w2p + warp * 2 * 64;
    ull acc0 = c_b2p[warp * 2 + 0];
    ull acc1 = c_b2p[warp * 2 + 1];
    #pragma unroll 8
    for (int c = 0; c < C_; c++) {
        ull fd = fdup(feat[lane][c]);
        acc0 = ffma2(fd, w2g[c], acc0);
        acc1 = ffma2(fd, w2g[64 + c], acc1);
    }

    // scatter-max into pooled output; signed-int max == float max for the
    // >=0 floor, and negative bit patterns lose to >=0 => free ReLU.
    const int  g  = g0 + lane;
    const int4 c4 = ((const int4*)coords)[g];   // x=batch, z=y, w=x
    const int  xo = c4.w / 100;
    int* oi = (int*)out;
    {
        float lo, hi;
        int c0 = warp * 4;
        funpack(acc0, lo, hi);
        atomicMax(&oi[((c4.x * C_ + c0) * NY_ + c4.z) * NXO_ + xo], __float_as_int(lo));
        atomicMax(&oi[((c4.x * C_ + c0 + 1) * NY_ + c4.z) * NXO_ + xo], __float_as_int(hi));
        funpack(acc1, lo, hi);
        atomicMax(&oi[((c4.x * C_ + c0 + 2) * NY_ + c4.z) * NXO_ + xo], __float_as_int(lo));
        atomicMax(&oi[((c4.x * C_ + c0 + 3) * NY_ + c4.z) * NXO_ + xo], __float_as_int(hi));
    }
}

// ---------------- launch ----------------
extern "C" void kernel_launch(void* const* d_in, const int* in_sizes, int n_in,
                              void* d_out, int out_size) {
    const float* x      = (const float*)d_in[0];
    const int*   coords = (const int*)d_in[1];
    const float* w1  = (const float*)d_in[2];
    const float* b1  = (const float*)d_in[3];
    const float* g1  = (const float*)d_in[4];
    const float* be1 = (const float*)d_in[5];
    const float* m1  = (const float*)d_in[6];
    const float* v1  = (const float*)d_in[7];
    const float* w2  = (const float*)d_in[8];
    const float* b2  = (const float*)d_in[9];
    const float* g2  = (const float*)d_in[10];
    const float* be2 = (const float*)d_in[11];
    const float* m2  = (const float*)d_in[12];
    const float* v2  = (const float*)d_in[13];
    float* out = (float*)d_out;

    k_setup<<<1, 1024>>>(w1, b1, g1, be1, m1, v1, w2, b2, g2, be2, m2, v2);

    // copy packed params into __constant__ (graph-capturable D2D memcpys)
    void *pc, *pg;
    cudaGetSymbolAddress(&pc, c_w1p); cudaGetSymbolAddress(&pg, g_w1p);
    cudaMemcpyAsync(pc, pg, sizeof(ull) * F_ * 32, cudaMemcpyDeviceToDevice, 0);
    cudaGetSymbolAddress(&pc, c_b1p); cudaGetSymbolAddress(&pg, g_b1p);
    cudaMemcpyAsync(pc, pg, sizeof(ull) * 32, cudaMemcpyDeviceToDevice, 0);
    cudaGetSymbolAddress(&pc, c_b2p); cudaGetSymbolAddress(&pg, g_b2p);
    cudaMemcpyAsync(pc, pg, sizeof(ull) * 32, cudaMemcpyDeviceToDevice, 0);
    cudaGetSymbolAddress(&pc, c_z);   cudaGetSymbolAddress(&pg, g_z);
    cudaMemcpyAsync(pc, pg, sizeof(float) * C_, cudaMemcpyDeviceToDevice, 0);

    k_init<<<(NOUT / 4 + 511) / 512, 512>>>(out);
    k_main<<<NPTS / NPB, TPB>>>(x, coords, out);
}

// round 7
// speedup vs baseline: 1.2059x; 1.2059x over previous
#include <cuda_runtime.h>
#include <cstdint>

typedef unsigned long long ull;

// ---------------- problem constants ----------------
#define B_   4
#define F_   9
#define MP_  100
#define P_   12000
#define C_   64
#define NY_  400
#define NX_  400
#define NXO_ 4          // NX / POOL_W
#define NPTS (B_ * P_)  // 48000
#define NOUT (B_ * C_ * NY_ * NXO_) // 409600
#define EPSF 1e-3f

// main kernel tiling
#define TPB  256
#define NPB  32          // points per block (one per lane)
#define MPT  10          // mp per chunk
#define NCH  (MP_ / MPT) // 10 chunks
#define NBUF 3           // pipeline depth
#define XSN  (F_ * MPT * NPB)   // 2880 floats staged per chunk
#define XSNB (XSN * 4)          // bytes per chunk buffer
#define CPOPS (XSN * 4 / 16)    // 720 cp.async 16B ops per chunk
#define CHF   (MPT * P_)        // float stride between chunks in gmem

// prep/init grid: block 0 packs weights, blocks 1..INIT_BLK init out
#define INIT_TPB 512
#define INIT_BLK (NOUT / 4 / INIT_TPB)   // 200

// ---------------- device scratch (no allocs allowed) ----------------
__device__ ull g_w1p[F_ * 32];   // packed pairs: [f][q] -> (w1'[2q][f], w1'[2q+1][f])
__device__ ull g_b1p[32];
__device__ ull g_w2p[32 * 64];   // [q][c] -> (w2'[2q][c], w2'[2q+1][c])
__device__ ull g_b2p[32];

// ---------------- f32x2 helpers (Blackwell packed fp32) ----------------
__device__ __forceinline__ ull ffma2(ull a, ull b, ull c) {
    ull d;
    asm("fma.rn.f32x2 %0, %1, %2, %3;" : "=l"(d) : "l"(a), "l"(b), "l"(c));
    return d;
}
__device__ __forceinline__ ull fpack(float x, float y) {
    ull r;
    asm("mov.b64 %0, {%1, %2};" : "=l"(r) : "f"(x), "f"(y));
    return r;
}
__device__ __forceinline__ ull fdup(float x) {
    ull r;
    asm("mov.b64 %0, {%1, %2};" : "=l"(r) : "f"(x), "f"(x));
    return r;
}
__device__ __forceinline__ void funpack(ull v, float& x, float& y) {
    asm("mov.b64 {%0, %1}, %2;" : "=f"(x), "=f"(y) : "l"(v));
}
__device__ __forceinline__ ull fmax2(ull a, ull b) {
    float ax, ay, bx, by;
    funpack(a, ax, ay);
    funpack(b, bx, by);
    return fpack(fmaxf(ax, bx), fmaxf(ay, by));
}
__device__ __forceinline__ uint32_t smem_u32(const void* p) {
    return (uint32_t)__cvta_generic_to_shared(p);
}
__device__ __forceinline__ void cp16(uint32_t dst, const float* src) {
    asm volatile("cp.async.cg.shared.global [%0], [%1], 16;" :: "r"(dst), "l"(src));
}

// ---------------- prep + init (single launch) ----------------
// Block 0: BN-fold + pack weights into g_* (read only by k_main, next launch).
// Blocks 1..INIT_BLK: init out = relu(b2') everywhere. Every 100-cell pool
// window contains an empty canvas cell (12000 pillars on 160000 cells;
// P(full window) ~ 1e-112), so the empty-cell constant is always a valid
// atomicMax floor. Each init thread derives z[c] locally -> no cross-block
// dependency inside this launch.
__global__ void k_prep(const float* __restrict__ w1, const float* __restrict__ b1,
                       const float* __restrict__ g1, const float* __restrict__ be1,
                       const float* __restrict__ m1, const float* __restrict__ v1,
                       const float* __restrict__ w2, const float* __restrict__ b2,
                       const float* __restrict__ g2, const float* __restrict__ be2,
                       const float* __restrict__ m2, const float* __restrict__ v2,
                       float* __restrict__ out) {
    if (blockIdx.x == 0) {
        __shared__ float s1[C_], bb1[C_], s2[C_], bb2[C_];
        int t = threadIdx.x;
        if (t < C_) {
            float s = g1[t] * rsqrtf(v1[t] + EPSF);
            s1[t] = s;
            bb1[t] = b1[t] * s + be1[t] - m1[t] * s;
            float ss = g2[t] * rsqrtf(v2[t] + EPSF);
            s2[t] = ss;
            bb2[t] = b2[t] * ss + be2[t] - m2[t] * ss;
        }
        __syncthreads();
        for (int i = t; i < F_ * 32; i += INIT_TPB) {
            int f = i / 32, q = i % 32;
            g_w1p[i] = fpack(w1[(2 * q) * F_ + f] * s1[2 * q],
                             w1[(2 * q + 1) * F_ + f] * s1[2 * q + 1]);
        }
        for (int i = t; i < 32 * 64; i += INIT_TPB) {
            int q = i / 64, c = i % 64;
            g_w2p[i] = fpack(w2[(2 * q) * C_ + c] * s2[2 * q],
                             w2[(2 * q + 1) * C_ + c] * s2[2 * q + 1]);
        }
        if (t < 32) {
            g_b1p[t] = fpack(bb1[2 * t], bb1[2 * t + 1]);
            g_b2p[t] = fpack(bb2[2 * t], bb2[2 * t + 1]);
        }
    } else {
        int i = (blockIdx.x - 1) * INIT_TPB + threadIdx.x;  // float4 index
        int c = (i / NY_) & (C_ - 1);
        float ss = g2[c] * rsqrtf(v2[c] + EPSF);
        float zc = fmaxf(b2[c] * ss + be2[c] - m2[c] * ss, 0.0f);
        ((float4*)out)[i] = make_float4(zc, zc, zc, zc);
    }
}

// ---------------- main fused kernel ----------------
// 8 warps; lane = point (32 points/block), warp owns 4 channel-pairs.
// x staged global->shared via 3-deep cp.async pipeline, ONE barrier/chunk.
// Bias-free accumulation (bias + ReLU folded in after the mp-max).
__global__ void __launch_bounds__(TPB, 2) k_main(const float* __restrict__ x,
                                                 const int* __restrict__ coords,
                                                 float* __restrict__ out) {
    __shared__ float xs[NBUF][XSN];
    __shared__ float feat[NPB][65];

    const int tid  = threadIdx.x;
    const int warp = tid >> 5;
    const int lane = tid & 31;
    const int g0   = blockIdx.x * NPB;      // first point id of block
    const int b    = g0 / P_;               // block never crosses batch
    const int pb   = g0 - b * P_;

    // stage-1 weights into registers (uniform within warp)
    ull w1r[4][F_];
    #pragma unroll
    for (int j = 0; j < 4; j++)
        #pragma unroll
        for (int f = 0; f < F_; f++)
            w1r[j][f] = g_w1p[f * 32 + warp * 4 + j];

    const float* xb = x + (size_t)b * (F_ * MP_ * P_) + pb;

    // cp.async assignment (fixed per thread): 720 16B ops/chunk, <=3/thread
    // idx -> f = idx/80, mpi = (idx%80)>>3, quad = idx&7
    const uint32_t xs_base = smem_u32(&xs[0][0]);
    int      cp_soff[3];
    uint32_t cp_doff[3];
    bool     cp_on[3];
    #pragma unroll
    for (int k = 0; k < 3; k++) {
        int idx = tid + k * TPB;
        cp_on[k] = idx < CPOPS;
        int ii   = cp_on[k] ? idx : 0;
        int f    = ii / (MPT * 8);
        int r    = ii - f * (MPT * 8);
        int mpi  = r >> 3;
        int q    = r & 7;
        cp_soff[k] = f * (MP_ * P_) + mpi * P_ + q * 4;
        cp_doff[k] = (uint32_t)(((f * MPT + mpi) * NPB + q * 4) * 4);
    }

    // prologue: prefetch chunks 0 and 1 into bufs 0,1
    #pragma unroll
    for (int k = 0; k < 3; k++)
        if (cp_on[k]) cp16(xs_base + cp_doff[k], xb + cp_soff[k]);
    asm volatile("cp.async.commit_group;");
    #pragma unroll
    for (int k = 0; k < 3; k++)
        if (cp_on[k]) cp16(xs_base + XSNB + cp_doff[k], xb + cp_soff[k] + CHF);
    asm volatile("cp.async.commit_group;");

    ull m[4];
    #pragma unroll
    for (int j = 0; j < 4; j++) m[j] = 0xFF800000FF800000ull;  // (-inf,-inf)

    int bufc = 0, bufn = 2;
    #pragma unroll 1
    for (int ch = 0; ch < NCH; ++ch) {
        if (ch < NCH - 1) asm volatile("cp.async.wait_group 1;");
        else              asm volatile("cp.async.wait_group 0;");
        __syncthreads();   // chunk ch visible; all done reading buf[bufn]

        if (ch + 2 < NCH) {   // prefetch chunk ch+2 into bufn
            uint32_t d = xs_base + (uint32_t)bufn * XSNB;
            const float* s = xb + (ch + 2) * CHF;
            #pragma unroll
            for (int k = 0; k < 3; k++)
                if (cp_on[k]) cp16(d + cp_doff[k], s + cp_soff[k]);
            asm volatile("cp.async.commit_group;");
        }

        const float* xc = &xs[bufc][0];
        #pragma unroll
        for (int mpi = 0; mpi < MPT; ++mpi) {
            ull xd0 = fdup(xc[(0 * MPT + mpi) * NPB + lane]);
            ull a0 = ffma2(xd0, w1r[0][0], 0ull);
            ull a1 = ffma2(xd0, w1r[1][0], 0ull);
            ull a2 = ffma2(xd0, w1r[2][0], 0ull);
            ull a3 = ffma2(xd0, w1r[3][0], 0ull);
            #pragma unroll
            for (int f = 1; f < F_; f++) {
                ull xd = fdup(xc[(f * MPT + mpi) * NPB + lane]);
                a0 = ffma2(xd, w1r[0][f], a0);
                a1 = ffma2(xd, w1r[1][f], a1);
                a2 = ffma2(xd, w1r[2][f], a2);
                a3 = ffma2(xd, w1r[3][f], a3);
            }
            m[0] = fmax2(m[0], a0);
            m[1] = fmax2(m[1], a1);
            m[2] = fmax2(m[2], a2);
            m[3] = fmax2(m[3], a3);
        }
        bufc = (bufc == NBUF - 1) ? 0 : bufc + 1;
        bufn = (bufn == NBUF - 1) ? 0 : bufn + 1;
    }

    // bias + ReLU after the max (exact: max_mp(Wx+b) = max_mp(Wx)+b),
    // exchange feat (point-major, padded 65 -> bank-conflict-free)
    #pragma unroll
    for (int j = 0; j < 4; j++) {
        float lo, hi, bl, bh;
        funpack(m[j], lo, hi);
        funpack(g_b1p[warp * 4 + j], bl, bh);
        int c0 = (warp * 4 + j) * 2;
        feat[lane][c0]     = fmaxf(lo + bl, 0.0f);
        feat[lane][c0 + 1] = fmaxf(hi + bh, 0.0f);
    }
    __syncthreads();

    // stage 2: 64->64 affine; w2 pairs straight from global (L1/L2 resident,
    // 16KB shared by all blocks)
    const ull* __restrict__ w2g = g_w2p + warp * 4 * 64;
    ull acc[4];
    #pragma unroll
    for (int j = 0; j < 4; j++) acc[j] = g_b2p[warp * 4 + j];
    #pragma unroll 8
    for (int c = 0; c < C_; c++) {
        ull fd = fdup(feat[lane][c]);
        #pragma unroll
        for (int j = 0; j < 4; j++)
            acc[j] = ffma2(fd, w2g[j * 64 + c], acc[j]);
    }

    // scatter-max into pooled output; signed-int max == float max for the
    // >=0 floor, and negative bit patterns lose to >=0 => free ReLU.
    const int  g  = g0 + lane;
    const int4 c4 = ((const int4*)coords)[g];   // x=batch, z=y, w=x
    const int  xo = c4.w / 100;
    int* oi = (int*)out;
    #pragma unroll
    for (int j = 0; j < 4; j++) {
        float lo, hi;
        funpack(acc[j], lo, hi);
        int c0 = (warp * 4 + j) * 2;
        atomicMax(&oi[((c4.x * C_ + c0) * NY_ + c4.z) * NXO_ + xo], __float_as_int(lo));
        atomicMax(&oi[((c4.x * C_ + c0 + 1) * NY_ + c4.z) * NXO_ + xo], __float_as_int(hi));
    }
}

// ---------------- launch ----------------
extern "C" void kernel_launch(void* const* d_in, const int* in_sizes, int n_in,
                              void* d_out, int out_size) {
    const float* x      = (const float*)d_in[0];
    const int*   coords = (const int*)d_in[1];
    const float* w1  = (const float*)d_in[2];
    const float* b1  = (const float*)d_in[3];
    const float* g1  = (const float*)d_in[4];
    const float* be1 = (const float*)d_in[5];
    const float* m1  = (const float*)d_in[6];
    const float* v1  = (const float*)d_in[7];
    const float* w2  = (const float*)d_in[8];
    const float* b2  = (const float*)d_in[9];
    const float* g2  = (const float*)d_in[10];
    const float* be2 = (const float*)d_in[11];
    const float* m2  = (const float*)d_in[12];
    const float* v2  = (const float*)d_in[13];
    float* out = (float*)d_out;

    k_prep<<<1 + INIT_BLK, INIT_TPB>>>(w1, b1, g1, be1, m1, v1,
                                       w2, b2, g2, be2, m2, v2, out);
    k_main<<<NPTS / NPB, TPB>>>(x, coords, out);
}